// round 5
// baseline (speedup 1.0000x reference)
#include <cuda_runtime.h>
#include <math.h>

#define BB   64
#define NPG  1024
#define NN   (BB * NPG)       // 65536 nodes
#define EE   (BB * 16384)     // 1048576 edges
#define EPG  16384            // edges per graph
#define INF  64
#define HIDF 128
#define OUTF 32

#define ADJ_ELEMS  ((size_t)BB * NPG * NPG)   // 67108864
#define MEAN_OFF   ADJ_ELEMS
#define LS_OFF     (ADJ_ELEMS + (size_t)NN * OUTF)

#define AGG_SMEM   (NPG * 32 * 4 + EPG * 4)   // 196608 B
// k_mlp dynamic smem: sH(128*132) + sA(32*132) + sW(32*128) + rs(128) + b1(128)
#define MLP_SMEM   ((128 * 132 + 32 * 132 + 32 * 128 + 256) * 4)   // 101888 B

// ---------------- scratch (static device globals; no runtime alloc) -------
__device__ float g_rs_out[NN];
__device__ float g_rs_in[NN];
__device__ int   g_rowptr[NN + 1];
__device__ int   g_csr[EE];
__device__ float g_a[NN * INF];    // aggregated+scaled input features
__device__ float g_p[NN * 64];     // (h * rs_out) @ [W2 | W3]
__device__ float g_q[NN * 64];     // aggregated p (pre-bias mean|log_std)
__device__ float g_z[NN * OUTF];   // latent z

typedef unsigned long long u64;

// ---------------- f32x2 helpers (FFMA2) -----------------------------------
__device__ __forceinline__ u64 pack2(float lo, float hi) {
    u64 r;
    asm("mov.b64 %0, {%1, %2};" : "=l"(r) : "f"(lo), "f"(hi));
    return r;
}
__device__ __forceinline__ u64 fma2(u64 a, u64 b, u64 c) {
    u64 d;
    asm("fma.rn.f32x2 %0, %1, %2, %3;" : "=l"(d) : "l"(a), "l"(b), "l"(c));
    return d;
}
__device__ __forceinline__ void unpack2(u64 v, float& a, float& b) {
    asm("mov.b64 {%0, %1}, %2;" : "=f"(a), "=f"(b) : "l"(v));
}
__device__ __forceinline__ float sigm(float x) {
    return __fdividef(1.0f, 1.0f + __expf(-x));   // MUFU.EX2 + MUFU.RCP
}

// ---------------- k_build: per-graph CSR (count+scan+scatter fused) -------
__global__ __launch_bounds__(1024) void k_build(const int* __restrict__ src,
                                                const int* __restrict__ dst) {
    __shared__ int s_cin[NPG];
    __shared__ int s_cout[NPG];
    __shared__ int s_scan[NPG];
    __shared__ int s_fill[NPG];
    int g = blockIdx.x, t = threadIdx.x;
    int base_n = g * NPG, base_e = g * EPG;

    s_cin[t] = 0; s_cout[t] = 0;
    __syncthreads();
#pragma unroll
    for (int it = 0; it < 16; it++) {
        int e = base_e + it * 1024 + t;
        atomicAdd(&s_cin[dst[e] - base_n], 1);
        atomicAdd(&s_cout[src[e] - base_n], 1);
    }
    __syncthreads();
    int v = s_cin[t];
    s_scan[t] = v;
    __syncthreads();
    for (int ofs = 1; ofs < 1024; ofs <<= 1) {
        int x = (t >= ofs) ? s_scan[t - ofs] : 0;
        __syncthreads();
        s_scan[t] += x;
        __syncthreads();
    }
    int excl = s_scan[t] - v;
    g_rowptr[base_n + t] = base_e + excl;
    g_rs_in[base_n + t]  = rsqrtf((float)max(v, 1));
    g_rs_out[base_n + t] = rsqrtf((float)max(s_cout[t], 1));
    s_fill[t] = excl;
    if (g == BB - 1 && t == 1023) g_rowptr[NN] = EE;
    __syncthreads();
#pragma unroll
    for (int it = 0; it < 16; it++) {
        int e = base_e + it * 1024 + t;
        int d = dst[e] - base_n;
        int pos = atomicAdd(&s_fill[d], 1);
        g_csr[base_e + pos] = src[e];
    }
}

// ---------------- smem-staged aggregation of input features ---------------
__global__ __launch_bounds__(1024) void k_agg1s(const float* __restrict__ feat) {
    extern __shared__ __align__(16) char s_raw[];
    float* s_f = (float*)s_raw;                    // 1024*32 floats
    int* s_csr = (int*)(s_raw + NPG * 32 * 4);     // 16384 ints
    int g = blockIdx.x, h = blockIdx.y;
    int base_n = g * NPG, base_e = g * EPG;
    int t = threadIdx.x;

#pragma unroll
    for (int it = 0; it < 8; it++) {
        int idx = it * 1024 + t;                   // 8192 float4s
        int row = idx >> 3, q = idx & 7;
        float rs = g_rs_out[base_n + row];
        float4 v = *(const float4*)&feat[(size_t)(base_n + row) * INF + h * 32 + q * 4];
        v.x *= rs; v.y *= rs; v.z *= rs; v.w *= rs;
        *(float4*)&s_f[row * 32 + q * 4] = v;
    }
#pragma unroll
    for (int it = 0; it < 4; it++) {
        ((int4*)s_csr)[it * 1024 + t] = ((const int4*)(g_csr + base_e))[it * 1024 + t];
    }
    __syncthreads();

    int warp = t >> 5, lane = t & 31;
#pragma unroll 1
    for (int i = 0; i < 32; i++) {
        int n = base_n + warp * 32 + i;
        int beg = g_rowptr[n] - base_e, end = g_rowptr[n + 1] - base_e;
        float a = 0.f;
        int e = beg;
        for (; e + 3 < end; e += 4) {
            int s0 = s_csr[e] - base_n,     s1 = s_csr[e + 1] - base_n;
            int s2 = s_csr[e + 2] - base_n, s3 = s_csr[e + 3] - base_n;
            a += (s_f[s0 * 32 + lane] + s_f[s1 * 32 + lane]) +
                 (s_f[s2 * 32 + lane] + s_f[s3 * 32 + lane]);
        }
        for (; e < end; e++) a += s_f[(s_csr[e] - base_n) * 32 + lane];
        g_a[(size_t)n * INF + h * 32 + lane] = a * g_rs_in[n];
    }
}

// ---------------- smem-staged aggregation of p -> q -----------------------
__global__ __launch_bounds__(1024) void k_agg2s() {
    extern __shared__ __align__(16) char s_raw[];
    float* s_f = (float*)s_raw;
    int* s_csr = (int*)(s_raw + NPG * 32 * 4);
    int g = blockIdx.x, h = blockIdx.y;
    int base_n = g * NPG, base_e = g * EPG;
    int t = threadIdx.x;

#pragma unroll
    for (int it = 0; it < 8; it++) {
        int idx = it * 1024 + t;
        int row = idx >> 3, q = idx & 7;
        float4 v = *(const float4*)&g_p[(size_t)(base_n + row) * 64 + h * 32 + q * 4];
        *(float4*)&s_f[row * 32 + q * 4] = v;
    }
#pragma unroll
    for (int it = 0; it < 4; it++) {
        ((int4*)s_csr)[it * 1024 + t] = ((const int4*)(g_csr + base_e))[it * 1024 + t];
    }
    __syncthreads();

    int warp = t >> 5, lane = t & 31;
#pragma unroll 1
    for (int i = 0; i < 32; i++) {
        int n = base_n + warp * 32 + i;
        int beg = g_rowptr[n] - base_e, end = g_rowptr[n + 1] - base_e;
        float a = 0.f;
        int e = beg;
        for (; e + 3 < end; e += 4) {
            int s0 = s_csr[e] - base_n,     s1 = s_csr[e + 1] - base_n;
            int s2 = s_csr[e + 2] - base_n, s3 = s_csr[e + 3] - base_n;
            a += (s_f[s0 * 32 + lane] + s_f[s1 * 32 + lane]) +
                 (s_f[s2 * 32 + lane] + s_f[s3 * 32 + lane]);
        }
        for (; e < end; e++) a += s_f[(s_csr[e] - base_n) * 32 + lane];
        g_q[(size_t)n * 64 + h * 32 + lane] = a * g_rs_in[n];
    }
}

// ---------------- z epilogue: mean/ls/z from q ----------------------------
__global__ __launch_bounds__(256) void k_z(const float* __restrict__ noise,
                                           const float* __restrict__ b2,
                                           const float* __restrict__ b3,
                                           float* __restrict__ out_mean,
                                           float* __restrict__ out_ls) {
    int idx = blockIdx.x * 256 + threadIdx.x;     // 0 .. NN*32-1
    int n = idx >> 5, l = idx & 31;
    float mean = g_q[(size_t)n * 64 + l] + b2[l];
    float ls   = g_q[(size_t)n * 64 + 32 + l] + b3[l];
    float z    = fmaf(noise[idx], __expf(ls), mean);
    out_mean[idx] = mean;
    out_ls[idx]   = ls;
    g_z[idx]      = z;
}

// ---------------- fused MLP: h=relu(aW1+b1); p=(h*rs)@[W2|W3] -------------
// block: 128 nodes; 256 thr; stage1 thread 8x8, stage2 thread 8x4;
// h kept in smem transposed+scaled -> no g_h round trip.
__global__ __launch_bounds__(256, 2) void k_mlp(const float* __restrict__ W1,
                                                const float* __restrict__ b1,
                                                const float* __restrict__ W2,
                                                const float* __restrict__ W3) {
    extern __shared__ __align__(16) char s_raw[];
    float* sH   = (float*)s_raw;               // 128*132 : h^T scaled
    float* sA   = sH + 128 * 132;              // 32*132  : a^T chunk
    float* sW   = sA + 32 * 132;               // 32*128 stage1 / 32*64 stage2
    float* s_rs = sW + 32 * 128;               // 128
    float* s_b1 = s_rs + 128;                  // 128

    int tid = threadIdx.x;
    int n0 = blockIdx.x * 128;
    if (tid < 128) {
        s_rs[tid] = g_rs_out[n0 + tid];
        s_b1[tid] = b1[tid];
    }
    int tx = tid & 15, ty = tid >> 4;

    // ---- stage 1: h = relu(a @ W1 + b1) ----
    u64 acc[8][4];
#pragma unroll
    for (int r = 0; r < 8; r++)
#pragma unroll
        for (int cp = 0; cp < 4; cp++) acc[r][cp] = 0ull;

    for (int kc = 0; kc < 2; kc++) {
        __syncthreads();
#pragma unroll
        for (int it = 0; it < 4; it++) {
            int idx = it * 256 + tid;              // float4 idx, 1024 total
            int r = idx >> 3, k4 = (idx & 7) * 4;
            float4 v = *(const float4*)&g_a[(size_t)(n0 + r) * INF + kc * 32 + k4];
            sA[(k4 + 0) * 132 + r] = v.x;
            sA[(k4 + 1) * 132 + r] = v.y;
            sA[(k4 + 2) * 132 + r] = v.z;
            sA[(k4 + 3) * 132 + r] = v.w;
        }
#pragma unroll
        for (int it = 0; it < 4; it++) {
            int idx = it * 256 + tid;
            ((float4*)sW)[idx] = ((const float4*)(W1 + kc * 32 * 128))[idx];
        }
        __syncthreads();
#pragma unroll 4
        for (int k = 0; k < 32; k++) {
            const float* Ak = &sA[k * 132];
            const float* Wk = &sW[k * 128];
            float4 a0 = *(const float4*)&Ak[ty * 8];
            float4 a1 = *(const float4*)&Ak[ty * 8 + 4];
            float4 w0 = *(const float4*)&Wk[tx * 8];
            float4 w1 = *(const float4*)&Wk[tx * 8 + 4];
            u64 bp[4] = {pack2(w0.x, w0.y), pack2(w0.z, w0.w),
                         pack2(w1.x, w1.y), pack2(w1.z, w1.w)};
            float ar[8] = {a0.x, a0.y, a0.z, a0.w, a1.x, a1.y, a1.z, a1.w};
#pragma unroll
            for (int r = 0; r < 8; r++) {
                u64 ab = pack2(ar[r], ar[r]);
#pragma unroll
                for (int cp = 0; cp < 4; cp++) acc[r][cp] = fma2(ab, bp[cp], acc[r][cp]);
            }
        }
    }
    __syncthreads();   // all stage-1 reads of sA/sW done before sH/sW reuse

    // epilogue: relu + bias, scale by rs_out, write transposed into sH[k][r]
#pragma unroll
    for (int r = 0; r < 8; r++) {
        int row = ty * 8 + r;
        float rs = s_rs[row];
#pragma unroll
        for (int cp = 0; cp < 4; cp++) {
            float x, y;
            unpack2(acc[r][cp], x, y);
            int c0 = tx * 8 + 2 * cp;
            x = fmaxf(x + s_b1[c0], 0.f) * rs;
            y = fmaxf(y + s_b1[c0 + 1], 0.f) * rs;
            sH[(c0) * 132 + row]     = x;
            sH[(c0 + 1) * 132 + row] = y;
        }
    }

    // ---- stage 2: p = hs @ [W2 | W3] ----
    u64 acc2[8][2];
#pragma unroll
    for (int r = 0; r < 8; r++) { acc2[r][0] = 0ull; acc2[r][1] = 0ull; }

    for (int kc = 0; kc < 4; kc++) {
        __syncthreads();
        {
            int idx = tid;                          // float4 idx, 512 total
#pragma unroll
            for (int it = 0; it < 2; it++, idx += 256) {
                int k = idx >> 4, c4 = (idx & 15) * 4;
                int kr = kc * 32 + k;
                float4 v;
                if (c4 < 32) v = *(const float4*)&W2[kr * 32 + c4];
                else         v = *(const float4*)&W3[kr * 32 + (c4 - 32)];
                *(float4*)&sW[k * 64 + c4] = v;
            }
        }
        __syncthreads();
#pragma unroll 4
        for (int k = 0; k < 32; k++) {
            const float* Ak = &sH[(kc * 32 + k) * 132];
            const float* Wk = &sW[k * 64];
            float4 a0 = *(const float4*)&Ak[ty * 8];
            float4 a1 = *(const float4*)&Ak[ty * 8 + 4];
            float4 w0 = *(const float4*)&Wk[tx * 4];
            u64 bp[2] = {pack2(w0.x, w0.y), pack2(w0.z, w0.w)};
            float ar[8] = {a0.x, a0.y, a0.z, a0.w, a1.x, a1.y, a1.z, a1.w};
#pragma unroll
            for (int r = 0; r < 8; r++) {
                u64 ab = pack2(ar[r], ar[r]);
                acc2[r][0] = fma2(ab, bp[0], acc2[r][0]);
                acc2[r][1] = fma2(ab, bp[1], acc2[r][1]);
            }
        }
    }
#pragma unroll
    for (int r = 0; r < 8; r++) {
        float v[4];
        unpack2(acc2[r][0], v[0], v[1]);
        unpack2(acc2[r][1], v[2], v[3]);
        *(float4*)&g_p[(size_t)(n0 + ty * 8 + r) * 64 + tx * 4] =
            make_float4(v[0], v[1], v[2], v[3]);
    }
}

// ---------------- adj = sigmoid(Z Z^T): upper-tri tiles + mirrored write --
__global__ __launch_bounds__(256, 2) void k_adj(float* __restrict__ out) {
    __shared__ __align__(16) float sA[32 * 132];
    __shared__ __align__(16) float sB[32 * 132];

    int g = blockIdx.y;
    int t = blockIdx.x, bi = 0;
    while (t >= 8 - bi) { t -= 8 - bi; bi++; }
    int bj = bi + t;
    int i0 = bi * 128, j0 = bj * 128;

    const float4* zA4 = (const float4*)(g_z + ((size_t)(g * NPG + i0)) * OUTF);
    const float4* zB4 = (const float4*)(g_z + ((size_t)(g * NPG + j0)) * OUTF);
    int tid = threadIdx.x;

#pragma unroll
    for (int it = 0; it < 4; it++) {
        int idx = it * 256 + tid;                  // float4 idx, 1024 total
        int r = idx >> 3, k4 = (idx & 7) * 4;
        float4 va = zA4[idx];
        float4 vb = zB4[idx];
        sA[(k4 + 0) * 132 + r] = va.x;
        sA[(k4 + 1) * 132 + r] = va.y;
        sA[(k4 + 2) * 132 + r] = va.z;
        sA[(k4 + 3) * 132 + r] = va.w;
        sB[(k4 + 0) * 132 + r] = vb.x;
        sB[(k4 + 1) * 132 + r] = vb.y;
        sB[(k4 + 2) * 132 + r] = vb.z;
        sB[(k4 + 3) * 132 + r] = vb.w;
    }
    __syncthreads();

    int tx = tid & 15, ty = tid >> 4;
    u64 acc[8][4];
#pragma unroll
    for (int r = 0; r < 8; r++)
#pragma unroll
        for (int cp = 0; cp < 4; cp++) acc[r][cp] = 0ull;

#pragma unroll 4
    for (int k = 0; k < 32; k++) {
        const float* Ak = &sA[k * 132];
        const float* Bk = &sB[k * 132];
        float4 a0 = *(const float4*)&Ak[ty * 8];
        float4 a1 = *(const float4*)&Ak[ty * 8 + 4];
        float4 b0 = *(const float4*)&Bk[tx * 8];
        float4 b1 = *(const float4*)&Bk[tx * 8 + 4];
        u64 bp[4] = {pack2(b0.x, b0.y), pack2(b0.z, b0.w),
                     pack2(b1.x, b1.y), pack2(b1.z, b1.w)};
        float ar[8] = {a0.x, a0.y, a0.z, a0.w, a1.x, a1.y, a1.z, a1.w};
#pragma unroll
        for (int r = 0; r < 8; r++) {
            u64 ab = pack2(ar[r], ar[r]);
#pragma unroll
            for (int cp = 0; cp < 4; cp++) acc[r][cp] = fma2(ab, bp[cp], acc[r][cp]);
        }
    }

    float m[8][8];
#pragma unroll
    for (int r = 0; r < 8; r++)
#pragma unroll
        for (int cp = 0; cp < 4; cp++) {
            float x, y;
            unpack2(acc[r][cp], x, y);
            m[r][2 * cp]     = sigm(x);
            m[r][2 * cp + 1] = sigm(y);
        }

    float* ob = out + ((size_t)(g * NPG + i0)) * NPG + j0;
#pragma unroll
    for (int r = 0; r < 8; r++) {
        float* o = &ob[(size_t)(ty * 8 + r) * NPG + tx * 8];
        *(float4*)&o[0] = make_float4(m[r][0], m[r][1], m[r][2], m[r][3]);
        *(float4*)&o[4] = make_float4(m[r][4], m[r][5], m[r][6], m[r][7]);
    }
    if (bi != bj) {
        float* obT = out + ((size_t)(g * NPG + j0)) * NPG + i0;
#pragma unroll
        for (int c = 0; c < 8; c++) {
            float* o = &obT[(size_t)(tx * 8 + c) * NPG + ty * 8];
            *(float4*)&o[0] = make_float4(m[0][c], m[1][c], m[2][c], m[3][c]);
            *(float4*)&o[4] = make_float4(m[4][c], m[5][c], m[6][c], m[7][c]);
        }
    }
}

// ---------------- launch ---------------------------------------------------
extern "C" void kernel_launch(void* const* d_in, const int* in_sizes, int n_in,
                              void* d_out, int out_size) {
    const float* features = (const float*)d_in[0];
    const int*   src      = (const int*)d_in[1];
    const int*   dst      = (const int*)d_in[2];
    const float* noise    = (const float*)d_in[3];
    const float* W1       = (const float*)d_in[4];
    const float* b1       = (const float*)d_in[5];
    const float* W2       = (const float*)d_in[6];
    const float* b2       = (const float*)d_in[7];
    const float* W3       = (const float*)d_in[8];
    const float* b3       = (const float*)d_in[9];

    float* out      = (float*)d_out;
    float* out_adj  = out;
    float* out_mean = out + MEAN_OFF;
    float* out_ls   = out + LS_OFF;

    static int smem_set = 0;
    if (!smem_set) {
        cudaFuncSetAttribute(k_agg1s, cudaFuncAttributeMaxDynamicSharedMemorySize, AGG_SMEM);
        cudaFuncSetAttribute(k_agg2s, cudaFuncAttributeMaxDynamicSharedMemorySize, AGG_SMEM);
        cudaFuncSetAttribute(k_mlp,   cudaFuncAttributeMaxDynamicSharedMemorySize, MLP_SMEM);
        smem_set = 1;
    }

    k_build<<<BB, 1024>>>(src, dst);
    k_agg1s<<<dim3(BB, 2), 1024, AGG_SMEM>>>(features);
    k_mlp<<<512, 256, MLP_SMEM>>>(W1, b1, W2, W3);
    k_agg2s<<<dim3(BB, 2), 1024, AGG_SMEM>>>();
    k_z<<<NN * 32 / 256, 256>>>(noise, b2, b3, out_mean, out_ls);
    k_adj<<<dim3(36, BB), 256>>>(out_adj);
}